// round 1
// baseline (speedup 1.0000x reference)
#include <cuda_runtime.h>

#define MDIM   1024
#define NHEADS 16
#define HDIM   64
#define BATCH  4
#define SEQ    2048
#define MROWS  (BATCH * SEQ)   // 8192

// ---------------- scratch (static device globals; no allocations) ----------
__device__ float g_qh[BATCH * NHEADS * SEQ * HDIM];   // [B,H,S,dh]
__device__ float g_kh[BATCH * NHEADS * SEQ * HDIM];
__device__ float g_vh[BATCH * NHEADS * SEQ * HDIM];
__device__ float g_ctx[BATCH * SEQ * MDIM];           // [B,S,H*dh] flat

// ---------------- GEMM: C = A(M,K) * W(N,K)^T -------------------------------
// BM=BN=128, BK=16, 256 threads, 8x8 per thread.
// HEAD_OUT: write C[m,n] into head layout qh[((b*H + n/64)*S + s)*64 + n%64]
//           with m = b*S + s. Otherwise flat C[m*N + n].
template<bool HEAD_OUT>
__global__ __launch_bounds__(256)
void gemm_kernel(const float* __restrict__ A,
                 const float* __restrict__ W,
                 float* __restrict__ C) {
    const int K = MDIM;
    const int N = MDIM;

    __shared__ float As[16][128];
    __shared__ float Bs[16][128];

    const int bn = blockIdx.x * 128;
    const int bm = blockIdx.y * 128;
    const int tid = threadIdx.x;
    const int tx = tid & 15;
    const int ty = tid >> 4;

    float acc[8][8] = {};

    for (int k0 = 0; k0 < K; k0 += 16) {
        // load A tile (128 rows x 16 k), 512 float4
        #pragma unroll
        for (int v = tid; v < 512; v += 256) {
            int m  = v >> 2;
            int kq = v & 3;
            float4 a = *(const float4*)(A + (size_t)(bm + m) * K + k0 + kq * 4);
            As[kq * 4 + 0][m] = a.x;
            As[kq * 4 + 1][m] = a.y;
            As[kq * 4 + 2][m] = a.z;
            As[kq * 4 + 3][m] = a.w;
        }
        // load W tile (128 n-rows x 16 k)
        #pragma unroll
        for (int v = tid; v < 512; v += 256) {
            int n  = v >> 2;
            int kq = v & 3;
            float4 b = *(const float4*)(W + (size_t)(bn + n) * K + k0 + kq * 4);
            Bs[kq * 4 + 0][n] = b.x;
            Bs[kq * 4 + 1][n] = b.y;
            Bs[kq * 4 + 2][n] = b.z;
            Bs[kq * 4 + 3][n] = b.w;
        }
        __syncthreads();

        #pragma unroll
        for (int kk = 0; kk < 16; kk++) {
            float a[8], b[8];
            float4 a0 = *(const float4*)&As[kk][ty * 8];
            float4 a1 = *(const float4*)&As[kk][ty * 8 + 4];
            float4 b0 = *(const float4*)&Bs[kk][tx * 8];
            float4 b1 = *(const float4*)&Bs[kk][tx * 8 + 4];
            a[0]=a0.x; a[1]=a0.y; a[2]=a0.z; a[3]=a0.w;
            a[4]=a1.x; a[5]=a1.y; a[6]=a1.z; a[7]=a1.w;
            b[0]=b0.x; b[1]=b0.y; b[2]=b0.z; b[3]=b0.w;
            b[4]=b1.x; b[5]=b1.y; b[6]=b1.z; b[7]=b1.w;
            #pragma unroll
            for (int i = 0; i < 8; i++)
                #pragma unroll
                for (int j = 0; j < 8; j++)
                    acc[i][j] = fmaf(a[i], b[j], acc[i][j]);
        }
        __syncthreads();
    }

    // store
    #pragma unroll
    for (int i = 0; i < 8; i++) {
        int m = bm + ty * 8 + i;
        #pragma unroll
        for (int j = 0; j < 8; j++) {
            int n = bn + tx * 8 + j;
            if (HEAD_OUT) {
                int b = m >> 11;        // m / SEQ
                int s = m & 2047;
                int h = n >> 6;
                int d = n & 63;
                C[(((size_t)(b * NHEADS + h) * SEQ) + s) * HDIM + d] = acc[i][j];
            } else {
                C[(size_t)m * N + n] = acc[i][j];
            }
        }
    }
}

// ---------------- Flash attention ------------------------------------------
// grid: (SEQ/64, B*H); block: 256 threads (16x16), each owns 4x4 of S and O.
// smem: Qs[64][65], KPs[64][65] (K then reused for P), Vs[64][65] -> 49920 B.
#define FLASH_SMEM (3 * 64 * 65 * 4)

__global__ __launch_bounds__(256)
void flash_kernel(const float* __restrict__ qh,
                  const float* __restrict__ kh,
                  const float* __restrict__ vh,
                  float* __restrict__ ctx) {
    extern __shared__ float sm[];
    float* Qs  = sm;               // [64][65]
    float* KPs = sm + 64 * 65;     // [64][65]
    float* Vs  = sm + 2 * 64 * 65; // [64][65]

    const int bh = blockIdx.y;
    const int b  = bh >> 4;
    const int h  = bh & 15;
    const int q0 = blockIdx.x * 64;

    const float* qb = qh + (size_t)bh * SEQ * HDIM;
    const float* kb = kh + (size_t)bh * SEQ * HDIM;
    const float* vb = vh + (size_t)bh * SEQ * HDIM;

    const int tid = threadIdx.x;
    const int tx = tid & 15;
    const int ty = tid >> 4;
    const int r0 = ty * 4;
    const int c0 = tx * 4;

    // load Q tile, pre-scaled by 1/sqrt(dh)
    for (int i = tid; i < 64 * HDIM; i += 256) {
        int r = i >> 6, d = i & 63;
        Qs[r * 65 + d] = qb[(size_t)(q0 + r) * HDIM + d] * 0.125f;
    }

    float m_run[4], l_run[4];
    float o[4][4] = {};
    #pragma unroll
    for (int i = 0; i < 4; i++) { m_run[i] = -1e30f; l_run[i] = 0.f; }

    for (int kt = 0; kt < SEQ / 64; kt++) {
        const int k0 = kt * 64;
        __syncthreads();   // protect K/V/P from previous iteration's readers
        for (int i = tid; i < 64 * HDIM; i += 256) {
            int r = i >> 6, d = i & 63;
            KPs[r * 65 + d] = kb[(size_t)(k0 + r) * HDIM + d];
            Vs [r * 65 + d] = vb[(size_t)(k0 + r) * HDIM + d];
        }
        __syncthreads();

        // S = Q K^T (4x4 per thread)
        float s[4][4] = {};
        #pragma unroll 8
        for (int d = 0; d < HDIM; d++) {
            float qv[4], kv[4];
            #pragma unroll
            for (int i = 0; i < 4; i++) qv[i] = Qs[(r0 + i) * 65 + d];
            #pragma unroll
            for (int j = 0; j < 4; j++) kv[j] = KPs[(c0 + j) * 65 + d];
            #pragma unroll
            for (int i = 0; i < 4; i++)
                #pragma unroll
                for (int j = 0; j < 4; j++)
                    s[i][j] = fmaf(qv[i], kv[j], s[i][j]);
        }

        // online softmax (rows owned by the 16 threads sharing ty)
        float p[4][4];
        #pragma unroll
        for (int i = 0; i < 4; i++) {
            float mx = s[i][0];
            #pragma unroll
            for (int j = 1; j < 4; j++) mx = fmaxf(mx, s[i][j]);
            #pragma unroll
            for (int off = 8; off >= 1; off >>= 1)
                mx = fmaxf(mx, __shfl_xor_sync(0xffffffffu, mx, off));
            float mn = fmaxf(m_run[i], mx);
            float sc = __expf(m_run[i] - mn);
            float rs = 0.f;
            #pragma unroll
            for (int j = 0; j < 4; j++) {
                p[i][j] = __expf(s[i][j] - mn);
                rs += p[i][j];
            }
            #pragma unroll
            for (int off = 8; off >= 1; off >>= 1)
                rs += __shfl_xor_sync(0xffffffffu, rs, off);
            l_run[i] = l_run[i] * sc + rs;
            m_run[i] = mn;
            #pragma unroll
            for (int j = 0; j < 4; j++) o[i][j] *= sc;
        }

        __syncthreads();   // everyone done reading K tile
        #pragma unroll
        for (int i = 0; i < 4; i++)
            #pragma unroll
            for (int j = 0; j < 4; j++)
                KPs[(r0 + i) * 65 + (c0 + j)] = p[i][j];
        __syncthreads();

        // O += P V (4x4 per thread; cols c0..c0+3 of dh)
        #pragma unroll 4
        for (int c = 0; c < 64; c++) {
            float pv[4], vv[4];
            #pragma unroll
            for (int i = 0; i < 4; i++) pv[i] = KPs[(r0 + i) * 65 + c];
            #pragma unroll
            for (int j = 0; j < 4; j++) vv[j] = Vs[c * 65 + c0 + j];
            #pragma unroll
            for (int i = 0; i < 4; i++)
                #pragma unroll
                for (int j = 0; j < 4; j++)
                    o[i][j] = fmaf(pv[i], vv[j], o[i][j]);
        }
    }

    // normalize + write ctx in flat [B,S,H*dh] layout
    #pragma unroll
    for (int i = 0; i < 4; i++) {
        float inv = 1.f / l_run[i];
        int row = q0 + r0 + i;
        #pragma unroll
        for (int j = 0; j < 4; j++)
            ctx[((size_t)(b * SEQ + row)) * MDIM + h * HDIM + c0 + j] = o[i][j] * inv;
    }
}

// ---------------- launch -----------------------------------------------------
extern "C" void kernel_launch(void* const* d_in, const int* in_sizes, int n_in,
                              void* d_out, int out_size) {
    const float* q  = (const float*)d_in[0];
    const float* k  = (const float*)d_in[1];
    const float* v  = (const float*)d_in[2];
    const float* wq = (const float*)d_in[3];
    const float* wk = (const float*)d_in[4];
    const float* wv = (const float*)d_in[5];
    const float* wo = (const float*)d_in[6];
    float* out = (float*)d_out;

    float *qh, *kh, *vh, *ctx;
    cudaGetSymbolAddress((void**)&qh,  g_qh);
    cudaGetSymbolAddress((void**)&kh,  g_kh);
    cudaGetSymbolAddress((void**)&vh,  g_vh);
    cudaGetSymbolAddress((void**)&ctx, g_ctx);

    cudaFuncSetAttribute(flash_kernel,
                         cudaFuncAttributeMaxDynamicSharedMemorySize, FLASH_SMEM);

    dim3 gridP(MDIM / 128, MROWS / 128);   // (8, 64)
    gemm_kernel<true ><<<gridP, 256>>>(q, wq, qh);
    gemm_kernel<true ><<<gridP, 256>>>(k, wk, kh);
    gemm_kernel<true ><<<gridP, 256>>>(v, wv, vh);

    dim3 gridF(SEQ / 64, BATCH * NHEADS); // (32, 64)
    flash_kernel<<<gridF, 256, FLASH_SMEM>>>(qh, kh, vh, ctx);

    gemm_kernel<false><<<gridP, 256>>>(ctx, wo, out);
}